// round 8
// baseline (speedup 1.0000x reference)
#include <cuda_runtime.h>
#include <cuda_bf16.h>
#include <math.h>

#define HD 256
#define NMAX 32768
#define EMAX 184320
#define MAXDEG 8

// ---------------- static scratch ----------------
__device__ float g_pd [EMAX];
__device__ float g_h  [(size_t)EMAX * HD];
__device__ float g_ea [(size_t)EMAX * HD];
__device__ float g_x  [(size_t)NMAX * HD];
__device__ float g_xa [(size_t)NMAX * HD];
__device__ float g_t  [(size_t)NMAX * HD];
__device__ float g_feat[(size_t)EMAX * 2 * HD];
__device__ float g_s1 [(size_t)EMAX * HD];
__device__ float g_s2 [(size_t)EMAX * (HD/2)];
__device__ int   g_cnt[NMAX];
__device__ int   g_csr[NMAX * MAXDEG];

// ---------------- SGEMM: C = epi(A[M,K] @ B[K,N] + bias) ----------------
// MODE 0: v=acc+bias; relu?          -> C
// MODE 1: v=acc+bias; relu?; v+=extra[m*N+n]  (residual) -> C
// MODE 2: v=(acc+bias)*extra[gidx[m]*N+n]             -> C
#define BM 64
#define BN 64
#define BK 16

template<int MODE, bool RELU>
__global__ __launch_bounds__(256) void sgemm(
    const float* __restrict__ A, const float* __restrict__ B,
    const float* __restrict__ bias, float* __restrict__ C,
    int M, int N, int K,
    const float* __restrict__ extra, const int* __restrict__ gidx)
{
    __shared__ float As[BM][BK];
    __shared__ float Bs[BK][BN];
    const int t  = threadIdx.x;
    const int tr = t >> 4, tc = t & 15;
    const int m0 = blockIdx.y * BM, n0 = blockIdx.x * BN;
    const int la_r = t >> 2,  la_c = (t & 3)  * 4;
    const int lb_r = t >> 4,  lb_c = (t & 15) * 4;

    float acc[4][4] = {};
    for (int k0 = 0; k0 < K; k0 += BK) {
        float4 av = make_float4(0.f, 0.f, 0.f, 0.f);
        if (m0 + la_r < M)
            av = *(const float4*)(A + (size_t)(m0 + la_r) * K + k0 + la_c);
        *(float4*)&As[la_r][la_c] = av;
        *(float4*)&Bs[lb_r][lb_c] =
            *(const float4*)(B + (size_t)(k0 + lb_r) * N + n0 + lb_c);
        __syncthreads();
#pragma unroll
        for (int kk = 0; kk < BK; kk++) {
            float a[4], b[4];
#pragma unroll
            for (int i = 0; i < 4; i++) a[i] = As[tr * 4 + i][kk];
            *(float4*)b = *(float4*)&Bs[kk][tc * 4];
#pragma unroll
            for (int i = 0; i < 4; i++)
#pragma unroll
                for (int j = 0; j < 4; j++)
                    acc[i][j] = fmaf(a[i], b[j], acc[i][j]);
        }
        __syncthreads();
    }

    float4 bv = *(const float4*)(bias + n0 + tc * 4);
    const float* bb = (const float*)&bv;
#pragma unroll
    for (int i = 0; i < 4; i++) {
        int m = m0 + tr * 4 + i;
        if (m >= M) continue;
        float4 ev = make_float4(0.f, 0.f, 0.f, 0.f);
        if (MODE == 1)
            ev = *(const float4*)(extra + (size_t)m * N + n0 + tc * 4);
        else if (MODE == 2)
            ev = *(const float4*)(extra + (size_t)gidx[m] * N + n0 + tc * 4);
        const float* ee = (const float*)&ev;
        float4 ov;
        float* oo = (float*)&ov;
#pragma unroll
        for (int j = 0; j < 4; j++) {
            float v = acc[i][j] + bb[j];
            if (MODE == 2) {
                v *= ee[j];
            } else {
                if (RELU) v = fmaxf(v, 0.f);
                if (MODE == 1) v += ee[j];
            }
            oo[j] = v;
        }
        *(float4*)(C + (size_t)m * N + n0 + tc * 4) = ov;
    }
}

// ---------------- elementwise / graph kernels ----------------
__global__ void edge_geom(const int* __restrict__ ei, const int* __restrict__ n2g,
                          const int* __restrict__ nl, const float* __restrict__ pos,
                          const float* __restrict__ dn, const float* __restrict__ sig,
                          int E) {
    int e = blockIdx.x * 256 + threadIdx.x;
    if (e >= E) return;
    int r = ei[e], c = ei[E + e];
    float dx = pos[3*r]   - pos[3*c];
    float dy = pos[3*r+1] - pos[3*c+1];
    float dz = pos[3*r+2] - pos[3*c+2];
    float d  = sqrtf(dx*dx + dy*dy + dz*dz);
    float us = sig[nl[n2g[r]]];
    g_pd[e] = fmaf(dn[e], us, d);
}

__global__ void build_h(const float* __restrict__ W1, const float* __restrict__ b1) {
    int e = blockIdx.x, k = threadIdx.x;
    g_h[(size_t)e * HD + k] = fmaxf(fmaf(g_pd[e], W1[k], b1[k]), 0.f);
}

__global__ void init_x(const int* __restrict__ atom, const float* __restrict__ nemb) {
    int i = blockIdx.x, k = threadIdx.x;
    g_x[(size_t)i * HD + k] = nemb[(size_t)atom[i] * HD + k];
}

__global__ void csr_zero(int N) {
    int i = blockIdx.x * 256 + threadIdx.x;
    if (i < N) g_cnt[i] = 0;
}

__global__ void csr_fill(const int* __restrict__ ei, int E) {
    int e = blockIdx.x * 256 + threadIdx.x;
    if (e >= E) return;
    int c = ei[E + e];
    int s = atomicAdd(&g_cnt[c], 1);
    if (s < MAXDEG) g_csr[c * MAXDEG + s] = e;
}

// sort each node's edge list ascending -> deterministic float sums
__global__ void csr_sort(int N) {
    int i = blockIdx.x * 256 + threadIdx.x;
    if (i >= N) return;
    int c = g_cnt[i]; if (c > MAXDEG) { c = MAXDEG; g_cnt[i] = MAXDEG; }
    int* p = &g_csr[i * MAXDEG];
    for (int a = 1; a < c; a++) {
        int v = p[a], b = a - 1;
        while (b >= 0 && p[b] > v) { p[b+1] = p[b]; b--; }
        p[b+1] = v;
    }
}

// xa[i] = x[i] + sum_{e: col(e)=i} relu(x[row(e)] + ea[e])
__global__ void agg_xa(const int* __restrict__ ei) {
    int i = blockIdx.x, k = threadIdx.x;
    float s = 0.f;
    int c = g_cnt[i];
#pragma unroll 1
    for (int d = 0; d < c; d++) {
        int e = g_csr[i * MAXDEG + d];
        int r = ei[e];
        s += fmaxf(g_x[(size_t)r * HD + k] + g_ea[(size_t)e * HD + k], 0.f);
    }
    g_xa[(size_t)i * HD + k] = g_x[(size_t)i * HD + k] + s;
}

__global__ void feat_build(const int* __restrict__ ei, int E) {
    int e = blockIdx.x, k = threadIdx.x;
    int r = ei[e], c = ei[E + e];
    g_feat[(size_t)e * 2 * HD + k]      = g_x[(size_t)r * HD + k] * g_x[(size_t)c * HD + k];
    g_feat[(size_t)e * 2 * HD + HD + k] = g_ea[(size_t)e * HD + k];
}

__global__ void zero_out(float* out, int G) {
    int i = blockIdx.x * 256 + threadIdx.x;
    if (i < G) out[i] = 0.f;
}

// s = dot(s2[e], W3) + b3 ; loss = 0.5*(s + dn[e])^2 -> atomicAdd(out[graph])
__global__ void edge_loss(const float* __restrict__ W3, const float* __restrict__ b3,
                          const float* __restrict__ dn, const int* __restrict__ ei,
                          const int* __restrict__ n2g, float* __restrict__ out, int E) {
    __shared__ float w3[HD/2];
    int t = threadIdx.x;
    if (t < HD/2) w3[t] = W3[t];
    __syncthreads();
    int warp = t >> 5, lane = t & 31;
    int e = blockIdx.x * 8 + warp;
    if (e >= E) return;
    const float* p = g_s2 + (size_t)e * (HD/2);
    float s = 0.f;
#pragma unroll
    for (int i = 0; i < 4; i++) s += p[lane + 32*i] * w3[lane + 32*i];
#pragma unroll
    for (int o = 16; o; o >>= 1) s += __shfl_xor_sync(0xFFFFFFFFu, s, o);
    if (lane == 0) {
        s += b3[0];
        float d = s + dn[e];
        atomicAdd(&out[n2g[ei[e]]], 0.5f * d * d);
    }
}

// ---------------- launch ----------------
extern "C" void kernel_launch(void* const* d_in, const int* in_sizes, int n_in,
                              void* d_out, int out_size) {
    const int*   atom = (const int*)  d_in[0];
    const int*   ei   = (const int*)  d_in[1];
    const int*   et   = (const int*)  d_in[2];
    const int*   n2g  = (const int*)  d_in[3];
    const int*   nl   = (const int*)  d_in[4];
    const float* pos  = (const float*)d_in[5];
    const float* dn   = (const float*)d_in[6];
    const float* sig  = (const float*)d_in[7];
    const float* nemb = (const float*)d_in[8];
    const float* eemb = (const float*)d_in[9];
    const float* inW1 = (const float*)d_in[10];
    const float* inb1 = (const float*)d_in[11];
    const float* inW2 = (const float*)d_in[12];
    const float* inb2 = (const float*)d_in[13];
    const float* gW1  = (const float*)d_in[14];
    const float* gb1  = (const float*)d_in[15];
    const float* gW2  = (const float*)d_in[16];
    const float* gb2  = (const float*)d_in[17];
    const float* oW1  = (const float*)d_in[18];
    const float* ob1  = (const float*)d_in[19];
    const float* oW2  = (const float*)d_in[20];
    const float* ob2  = (const float*)d_in[21];
    const float* oW3  = (const float*)d_in[22];
    const float* ob3  = (const float*)d_in[23];
    float* out = (float*)d_out;

    const int N = in_sizes[0];
    const int E = in_sizes[2];
    const int G = out_size;

    float *p_h, *p_ea, *p_x, *p_xa, *p_t, *p_feat, *p_s1, *p_s2;
    cudaGetSymbolAddress((void**)&p_h,    g_h);
    cudaGetSymbolAddress((void**)&p_ea,   g_ea);
    cudaGetSymbolAddress((void**)&p_x,    g_x);
    cudaGetSymbolAddress((void**)&p_xa,   g_xa);
    cudaGetSymbolAddress((void**)&p_t,    g_t);
    cudaGetSymbolAddress((void**)&p_feat, g_feat);
    cudaGetSymbolAddress((void**)&p_s1,   g_s1);
    cudaGetSymbolAddress((void**)&p_s2,   g_s2);

    dim3 gE(HD / BN, (E + BM - 1) / BM);       // [E,256] outputs
    dim3 gN(HD / BN, (N + BM - 1) / BM);       // [N,256] outputs
    dim3 gS2((HD/2) / BN, (E + BM - 1) / BM);  // [E,128] outputs

    // edge features
    edge_geom<<<(E + 255) / 256, 256>>>(ei, n2g, nl, pos, dn, sig, E);
    build_h<<<E, HD>>>(inW1, inb1);
    sgemm<2, false><<<gE, 256>>>(p_h, inW2, inb2, p_ea, E, HD, HD, eemb, et);

    // node init + CSR
    init_x<<<N, HD>>>(atom, nemb);
    csr_zero<<<(N + 255) / 256, 256>>>(N);
    csr_fill<<<(E + 255) / 256, 256>>>(ei, E);
    csr_sort<<<(N + 255) / 256, 256>>>(N);

    // GIN convs
    for (int c = 0; c < 4; c++) {
        agg_xa<<<N, HD>>>(ei);
        sgemm<0, true><<<gN, 256>>>(p_xa, gW1 + (size_t)c * HD * HD,
                                    gb1 + c * HD, p_t, N, HD, HD, nullptr, nullptr);
        if (c < 3)
            sgemm<1, true><<<gN, 256>>>(p_t, gW2 + (size_t)c * HD * HD,
                                        gb2 + c * HD, p_x, N, HD, HD, p_x, nullptr);
        else
            sgemm<1, false><<<gN, 256>>>(p_t, gW2 + (size_t)c * HD * HD,
                                         gb2 + c * HD, p_x, N, HD, HD, p_x, nullptr);
    }

    // edge score head
    feat_build<<<E, HD>>>(ei, E);
    sgemm<0, true><<<gE, 256>>>(p_feat, oW1, ob1, p_s1, E, HD, 2 * HD, nullptr, nullptr);
    sgemm<0, true><<<gS2, 256>>>(p_s1, oW2, ob2, p_s2, E, HD / 2, HD, nullptr, nullptr);

    zero_out<<<(G + 255) / 256, 256>>>(out, G);
    edge_loss<<<(E + 7) / 8, 256>>>(oW3, ob3, dn, ei, n2g, out, E);
}

// round 11
// speedup vs baseline: 1.3750x; 1.3750x over previous
#include <cuda_runtime.h>
#include <cuda_bf16.h>
#include <math.h>

#define HD 256
#define NMAX 32768
#define EMAX 184320
#define MAXDEG 8

typedef unsigned long long u64t;

// ---------------- static scratch ----------------
__device__ float g_pd [EMAX];
__device__ float g_ea [(size_t)EMAX * HD];
__device__ float g_x  [(size_t)NMAX * HD];
__device__ float g_xa [(size_t)NMAX * HD];
__device__ float g_t  [(size_t)NMAX * HD];
__device__ float g_s1 [(size_t)EMAX * HD];
__device__ float g_s2 [(size_t)EMAX * (HD/2)];
__device__ int   g_cnt[NMAX];
__device__ int   g_csr[NMAX * MAXDEG];

// ---------------- packed f32x2 helpers ----------------
__device__ __forceinline__ u64t pack2(float x) {
    u64t r; asm("mov.b64 %0, {%1, %1};" : "=l"(r) : "f"(x)); return r;
}
__device__ __forceinline__ void ffma2(u64t& d, u64t a, u64t b) {
    asm("fma.rn.f32x2 %0, %1, %2, %0;" : "+l"(d) : "l"(a), "l"(b));
}
__device__ __forceinline__ void unpack2(u64t v, float& lo, float& hi) {
    asm("mov.b64 {%0, %1}, %2;" : "=f"(lo), "=f"(hi) : "l"(v));
}

// ---------------- FFMA2 SGEMM: C = epi(A[M,K] @ B[K,N] + bias) ----------------
// MODE 0: v=acc+bias; relu?                         -> C
// MODE 1: v=acc+bias; relu?; v+=extra[m*N+n]        -> C   (residual)
// MODE 2: v=(acc+bias)*extra[gidx[m]*N+n]           -> C   (edge-emb mult)
// ASRC 0: A from global (row-major [M,K])
// ASRC 1: A[m][k] = relu(pd[m]*W1[k] + b1[k])       (d_emb hidden, on-the-fly)
// ASRC 2: A[m][k] = k<HD ? x[row[m]][k]*x[col[m]][k] : ea[m][k-HD]  (head feat)
//         (A = x base, extra = ea base, ei = edge_index, E = #edges)
#define BM 128
#define BN 128
#define BK 16
#define PAD 132

template<int MODE, bool RELU, int ASRC>
__global__ __launch_bounds__(256, 2) void gemm2(
    const float* __restrict__ A, const float* __restrict__ B,
    const float* __restrict__ bias, float* __restrict__ C,
    int M, int N, int K,
    const float* __restrict__ extra, const int* __restrict__ gidx,
    const float* __restrict__ pd, const float* __restrict__ W1,
    const float* __restrict__ b1, const int* __restrict__ ei, int E)
{
    __shared__ float As[BK][PAD];   // transposed: As[k][m]
    __shared__ float Bs[BK][PAD];
    const int t   = threadIdx.x;
    const int m0  = blockIdx.y * BM, n0 = blockIdx.x * BN;
    const int tr4 = (t >> 4) * 4,  tc4 = (t & 15) * 4;
    const int ar  = t >> 1,        akc = (t & 1) * 8;   // A-load: row, k-chunk
    const int bkr = t >> 4,        bnc = (t & 15) * 8;  // B-load: k-row, n-chunk
    const int am  = m0 + ar;

    u64t acc[8][4];
#pragma unroll
    for (int i = 0; i < 8; i++)
#pragma unroll
        for (int j = 0; j < 4; j++) acc[i][j] = 0ull;

    for (int k0 = 0; k0 < K; k0 += BK) {
        // ---- A tile (transposed into As) ----
        float v[8];
        if (am < M) {
            if (ASRC == 0) {
                *(float4*)&v[0] = *(const float4*)(A + (size_t)am * K + k0 + akc);
                *(float4*)&v[4] = *(const float4*)(A + (size_t)am * K + k0 + akc + 4);
            } else if (ASRC == 1) {
                const float p = pd[am];
#pragma unroll
                for (int j = 0; j < 8; j++)
                    v[j] = fmaxf(fmaf(p, W1[k0 + akc + j], b1[k0 + akc + j]), 0.f);
            } else {
                const int kg = k0 + akc;
                if (kg < HD) {
                    const int rr = ei[am], cc = ei[E + am];
                    float4 x0 = *(const float4*)(A + (size_t)rr * HD + kg);
                    float4 y0 = *(const float4*)(A + (size_t)cc * HD + kg);
                    float4 x1 = *(const float4*)(A + (size_t)rr * HD + kg + 4);
                    float4 y1 = *(const float4*)(A + (size_t)cc * HD + kg + 4);
                    v[0] = x0.x * y0.x; v[1] = x0.y * y0.y;
                    v[2] = x0.z * y0.z; v[3] = x0.w * y0.w;
                    v[4] = x1.x * y1.x; v[5] = x1.y * y1.y;
                    v[6] = x1.z * y1.z; v[7] = x1.w * y1.w;
                } else {
                    *(float4*)&v[0] = *(const float4*)(extra + (size_t)am * HD + kg - HD);
                    *(float4*)&v[4] = *(const float4*)(extra + (size_t)am * HD + kg - HD + 4);
                }
            }
        } else {
#pragma unroll
            for (int j = 0; j < 8; j++) v[j] = 0.f;
        }
        // ---- B tile (direct) ----
        float4 bv0 = *(const float4*)(B + (size_t)(k0 + bkr) * N + n0 + bnc);
        float4 bv1 = *(const float4*)(B + (size_t)(k0 + bkr) * N + n0 + bnc + 4);
        __syncthreads();  // protect previous iteration's reads
#pragma unroll
        for (int j = 0; j < 8; j++) As[akc + j][ar] = v[j];
        *(float4*)&Bs[bkr][bnc]     = bv0;
        *(float4*)&Bs[bkr][bnc + 4] = bv1;
        __syncthreads();

        // ---- mainloop: 32 FFMA2 per kk per thread ----
#pragma unroll
        for (int kk = 0; kk < BK; kk++) {
            float4 a0 = *(float4*)&As[kk][tr4];
            float4 a1 = *(float4*)&As[kk][tr4 + 64];
            ulonglong2 b0 = *(ulonglong2*)&Bs[kk][tc4];
            ulonglong2 b1v = *(ulonglong2*)&Bs[kk][tc4 + 64];
            u64t bb[4] = { b0.x, b0.y, b1v.x, b1v.y };
            u64t aa[8] = { pack2(a0.x), pack2(a0.y), pack2(a0.z), pack2(a0.w),
                           pack2(a1.x), pack2(a1.y), pack2(a1.z), pack2(a1.w) };
#pragma unroll
            for (int i = 0; i < 8; i++)
#pragma unroll
                for (int j = 0; j < 4; j++)
                    ffma2(acc[i][j], aa[i], bb[j]);
        }
    }

    // ---- epilogue ----
    float bb0[4], bb1[4];
    *(float4*)bb0 = *(const float4*)(bias + n0 + tc4);
    *(float4*)bb1 = *(const float4*)(bias + n0 + tc4 + 64);
#pragma unroll
    for (int i = 0; i < 8; i++) {
        const int m = m0 + tr4 + (i < 4 ? i : 60 + i);
        if (m >= M) continue;
        float v[8];
        unpack2(acc[i][0], v[0], v[1]); unpack2(acc[i][1], v[2], v[3]);
        unpack2(acc[i][2], v[4], v[5]); unpack2(acc[i][3], v[6], v[7]);
        float ex[8];
        if (MODE == 1) {
            *(float4*)&ex[0] = *(const float4*)(extra + (size_t)m * N + n0 + tc4);
            *(float4*)&ex[4] = *(const float4*)(extra + (size_t)m * N + n0 + tc4 + 64);
        } else if (MODE == 2) {
            const float* em = extra + (size_t)gidx[m] * N;
            *(float4*)&ex[0] = *(const float4*)(em + n0 + tc4);
            *(float4*)&ex[4] = *(const float4*)(em + n0 + tc4 + 64);
        }
        float o[8];
#pragma unroll
        for (int j = 0; j < 8; j++) {
            float val = v[j] + (j < 4 ? bb0[j] : bb1[j - 4]);
            if (MODE == 2) {
                val *= ex[j];
            } else {
                if (RELU) val = fmaxf(val, 0.f);
                if (MODE == 1) val += ex[j];
            }
            o[j] = val;
        }
        *(float4*)(C + (size_t)m * N + n0 + tc4)      = *(float4*)&o[0];
        *(float4*)(C + (size_t)m * N + n0 + tc4 + 64) = *(float4*)&o[4];
    }
}

// ---------------- elementwise / graph kernels ----------------
__global__ void edge_geom(const int* __restrict__ ei, const int* __restrict__ n2g,
                          const int* __restrict__ nl, const float* __restrict__ pos,
                          const float* __restrict__ dn, const float* __restrict__ sig,
                          int E) {
    int e = blockIdx.x * 256 + threadIdx.x;
    if (e >= E) return;
    int r = ei[e], c = ei[E + e];
    float dx = pos[3*r]   - pos[3*c];
    float dy = pos[3*r+1] - pos[3*c+1];
    float dz = pos[3*r+2] - pos[3*c+2];
    float d  = sqrtf(dx*dx + dy*dy + dz*dz);
    float us = sig[nl[n2g[r]]];
    g_pd[e] = fmaf(dn[e], us, d);
}

__global__ void init_x(const int* __restrict__ atom, const float* __restrict__ nemb) {
    int i = blockIdx.x, k = threadIdx.x;
    g_x[(size_t)i * HD + k] = nemb[(size_t)atom[i] * HD + k];
}

__global__ void csr_zero(int N) {
    int i = blockIdx.x * 256 + threadIdx.x;
    if (i < N) g_cnt[i] = 0;
}

__global__ void csr_fill(const int* __restrict__ ei, int E) {
    int e = blockIdx.x * 256 + threadIdx.x;
    if (e >= E) return;
    int c = ei[E + e];
    int s = atomicAdd(&g_cnt[c], 1);
    if (s < MAXDEG) g_csr[c * MAXDEG + s] = e;
}

// sort each node's edge list ascending -> deterministic float sums
__global__ void csr_sort(int N) {
    int i = blockIdx.x * 256 + threadIdx.x;
    if (i >= N) return;
    int c = g_cnt[i]; if (c > MAXDEG) { c = MAXDEG; g_cnt[i] = MAXDEG; }
    int* p = &g_csr[i * MAXDEG];
    for (int a = 1; a < c; a++) {
        int v = p[a], b = a - 1;
        while (b >= 0 && p[b] > v) { p[b+1] = p[b]; b--; }
        p[b+1] = v;
    }
}

// xa[i] = x[i] + sum_{e: col(e)=i} relu(x[row(e)] + ea[e])
__global__ void agg_xa(const int* __restrict__ ei) {
    int i = blockIdx.x, k = threadIdx.x;
    float s = 0.f;
    int c = g_cnt[i];
#pragma unroll 1
    for (int d = 0; d < c; d++) {
        int e = g_csr[i * MAXDEG + d];
        int r = ei[e];
        s += fmaxf(g_x[(size_t)r * HD + k] + g_ea[(size_t)e * HD + k], 0.f);
    }
    g_xa[(size_t)i * HD + k] = g_x[(size_t)i * HD + k] + s;
}

__global__ void zero_out(float* out, int G) {
    int i = blockIdx.x * 256 + threadIdx.x;
    if (i < G) out[i] = 0.f;
}

// s = dot(s2[e], W3) + b3 ; loss = 0.5*(s + dn[e])^2 -> atomicAdd(out[graph])
__global__ void edge_loss(const float* __restrict__ W3, const float* __restrict__ b3,
                          const float* __restrict__ dn, const int* __restrict__ ei,
                          const int* __restrict__ n2g, float* __restrict__ out, int E) {
    __shared__ float w3[HD/2];
    int t = threadIdx.x;
    if (t < HD/2) w3[t] = W3[t];
    __syncthreads();
    int warp = t >> 5, lane = t & 31;
    int e = blockIdx.x * 8 + warp;
    if (e >= E) return;
    const float* p = g_s2 + (size_t)e * (HD/2);
    float s = 0.f;
#pragma unroll
    for (int i = 0; i < 4; i++) s += p[lane + 32*i] * w3[lane + 32*i];
#pragma unroll
    for (int o = 16; o; o >>= 1) s += __shfl_xor_sync(0xFFFFFFFFu, s, o);
    if (lane == 0) {
        s += b3[0];
        float d = s + dn[e];
        atomicAdd(&out[n2g[ei[e]]], 0.5f * d * d);
    }
}

// ---------------- launch ----------------
extern "C" void kernel_launch(void* const* d_in, const int* in_sizes, int n_in,
                              void* d_out, int out_size) {
    const int*   atom = (const int*)  d_in[0];
    const int*   ei   = (const int*)  d_in[1];
    const int*   et   = (const int*)  d_in[2];
    const int*   n2g  = (const int*)  d_in[3];
    const int*   nl   = (const int*)  d_in[4];
    const float* pos  = (const float*)d_in[5];
    const float* dn   = (const float*)d_in[6];
    const float* sig  = (const float*)d_in[7];
    const float* nemb = (const float*)d_in[8];
    const float* eemb = (const float*)d_in[9];
    const float* inW1 = (const float*)d_in[10];
    const float* inb1 = (const float*)d_in[11];
    const float* inW2 = (const float*)d_in[12];
    const float* inb2 = (const float*)d_in[13];
    const float* gW1  = (const float*)d_in[14];
    const float* gb1  = (const float*)d_in[15];
    const float* gW2  = (const float*)d_in[16];
    const float* gb2  = (const float*)d_in[17];
    const float* oW1  = (const float*)d_in[18];
    const float* ob1  = (const float*)d_in[19];
    const float* oW2  = (const float*)d_in[20];
    const float* ob2  = (const float*)d_in[21];
    const float* oW3  = (const float*)d_in[22];
    const float* ob3  = (const float*)d_in[23];
    float* out = (float*)d_out;

    const int N = in_sizes[0];
    const int E = in_sizes[2];
    const int G = out_size;

    float *p_pd, *p_ea, *p_x, *p_xa, *p_t, *p_s1, *p_s2;
    cudaGetSymbolAddress((void**)&p_pd, g_pd);
    cudaGetSymbolAddress((void**)&p_ea, g_ea);
    cudaGetSymbolAddress((void**)&p_x,  g_x);
    cudaGetSymbolAddress((void**)&p_xa, g_xa);
    cudaGetSymbolAddress((void**)&p_t,  g_t);
    cudaGetSymbolAddress((void**)&p_s1, g_s1);
    cudaGetSymbolAddress((void**)&p_s2, g_s2);

    dim3 gE(HD / BN, (E + BM - 1) / BM);       // [E,256]
    dim3 gN(HD / BN, (N + BM - 1) / BM);       // [N,256]
    dim3 gS2((HD/2) / BN, (E + BM - 1) / BM);  // [E,128]

    // edge features: ea = (relu(pd @ W1 + b1) @ W2 + b2) * eemb[et]
    edge_geom<<<(E + 255) / 256, 256>>>(ei, n2g, nl, pos, dn, sig, E);
    gemm2<2, false, 1><<<gE, 256>>>(nullptr, inW2, inb2, p_ea, E, HD, HD,
                                    eemb, et, p_pd, inW1, inb1, nullptr, 0);

    // node init + CSR
    init_x<<<N, HD>>>(atom, nemb);
    csr_zero<<<(N + 255) / 256, 256>>>(N);
    csr_fill<<<(E + 255) / 256, 256>>>(ei, E);
    csr_sort<<<(N + 255) / 256, 256>>>(N);

    // GIN convs
    for (int c = 0; c < 4; c++) {
        agg_xa<<<N, HD>>>(ei);
        gemm2<0, true, 0><<<gN, 256>>>(p_xa, gW1 + (size_t)c * HD * HD,
                                       gb1 + c * HD, p_t, N, HD, HD,
                                       nullptr, nullptr, nullptr, nullptr, nullptr, nullptr, 0);
        if (c < 3)
            gemm2<1, true, 0><<<gN, 256>>>(p_t, gW2 + (size_t)c * HD * HD,
                                           gb2 + c * HD, p_x, N, HD, HD,
                                           p_x, nullptr, nullptr, nullptr, nullptr, nullptr, 0);
        else
            gemm2<1, false, 0><<<gN, 256>>>(p_t, gW2 + (size_t)c * HD * HD,
                                            gb2 + c * HD, p_x, N, HD, HD,
                                            p_x, nullptr, nullptr, nullptr, nullptr, nullptr, 0);
    }

    // edge score head (feat gathered on-the-fly inside GEMM)
    gemm2<0, true, 2><<<gE, 256>>>(p_x, oW1, ob1, p_s1, E, HD, 2 * HD,
                                   p_ea, nullptr, nullptr, nullptr, nullptr, ei, E);
    gemm2<0, true, 0><<<gS2, 256>>>(p_s1, oW2, ob2, p_s2, E, HD / 2, HD,
                                    nullptr, nullptr, nullptr, nullptr, nullptr, nullptr, 0);

    zero_out<<<(G + 255) / 256, 256>>>(out, G);
    edge_loss<<<(E + 7) / 8, 256>>>(oW3, ob3, dn, ei, n2g, out, E);
}

// round 17
// speedup vs baseline: 2.3026x; 1.6747x over previous
#include <cuda_runtime.h>
#include <cuda_bf16.h>
#include <math.h>
#include <stdint.h>

#define HD 256
#define NMAX 32768
#define EMAX 184320
#define MAXDEG 8

// ---------------- static scratch (fp32 activations) ----------------
__device__ float g_pd [EMAX];
__device__ float g_ea [(size_t)EMAX * HD];
__device__ float g_x  [(size_t)NMAX * HD];
__device__ float g_xa [(size_t)NMAX * HD];
__device__ float g_t  [(size_t)NMAX * HD];
__device__ float g_s1 [(size_t)EMAX * HD];
__device__ float g_s2 [(size_t)EMAX * (HD/2)];
__device__ int   g_cnt[NMAX];
__device__ int   g_csr[NMAX * MAXDEG];

// transposed, tf32-prerounded weights: [N][K] layout, fp32 bits
#define W_IN2   0
#define W_G1(c) ((1 + (c)) * 65536)
#define W_G2(c) ((5 + (c)) * 65536)
#define W_O1    589824
#define W_O2    720896
#define W_TOTAL 753664
__device__ float g_W[W_TOTAL];

// ---------------- tf32 mma helpers (baseline PTX) ----------------
__device__ __forceinline__ uint32_t f2tf(float f) {
    uint32_t r; asm("cvt.rna.tf32.f32 %0, %1;" : "=r"(r) : "f"(f)); return r;
}
__device__ __forceinline__ void mma_tf32(float* c, uint32_t a0, uint32_t a1,
                                         uint32_t a2, uint32_t a3,
                                         uint32_t b0, uint32_t b1) {
    asm("mma.sync.aligned.m16n8k8.row.col.f32.tf32.tf32.f32 "
        "{%0,%1,%2,%3}, {%4,%5,%6,%7}, {%8,%9}, {%0,%1,%2,%3};"
        : "+f"(c[0]), "+f"(c[1]), "+f"(c[2]), "+f"(c[3])
        : "r"(a0), "r"(a1), "r"(a2), "r"(a3), "r"(b0), "r"(b1));
}

// ---------------- tf32 tensor GEMM: C = epi(A[M,K] @ Bt[N,K]^T + bias) ------
// MODE 0: v=acc+bias; relu?                       -> C
// MODE 1: v=acc+bias; relu?; v+=extra[m*N+n]      -> C (residual)
// MODE 2: v=(acc+bias)*extra[gidx[m]*N+n]         -> C (edge-emb mult)
// ASRC 0: A fp32 global [M][K]
// ASRC 1: A[m][k] = relu(pd[m]*W1f[k]+b1f[k])     (d_emb hidden)
// ASRC 2: A[m][k] = k<HD ? x[row]*x[col] : ea[m][k-HD]  (head feat; A=x, extra2=ea)
// M, N multiples of 128; K multiple of 32. Bt is tf32-prerounded.
#define SKA 36   // smem row stride in floats: (m*36+c) mod 32 = 4m+c -> conflict-free

template<int MODE, bool RELU, int ASRC>
__global__ __launch_bounds__(256, 2) void tgemm(
    const float* __restrict__ A, const float* __restrict__ Bt,
    const float* __restrict__ bias, float* __restrict__ C,
    int M, int N, int K,
    const float* __restrict__ extra, const int* __restrict__ gidx,
    const float* __restrict__ pd, const float* __restrict__ W1f,
    const float* __restrict__ b1f, const int* __restrict__ ei, int E,
    const float* __restrict__ extra2)
{
    __shared__ uint32_t sA[128 * SKA];
    __shared__ uint32_t sB[128 * SKA];
    const int t = threadIdx.x, lane = t & 31, wid = t >> 5;
    const int wy = wid >> 2, wx = wid & 3;          // warp grid 2m x 4n
    const int m0 = blockIdx.y * 128, n0 = blockIdx.x * 128;

    const int ar = t >> 1, ah = t & 1;              // stage: row, 16-elem half
    const int am = m0 + ar;
    int rr = 0, cc = 0;
    if (ASRC == 2) { rr = ei[am]; cc = ei[E + am]; }

    float acc[4][4][4];
#pragma unroll
    for (int i = 0; i < 4; i++)
#pragma unroll
        for (int j = 0; j < 4; j++)
#pragma unroll
            for (int q = 0; q < 4; q++) acc[i][j][q] = 0.f;

    for (int k0 = 0; k0 < K; k0 += 32) {
        // ---- stage A: 16 floats -> tf32 ----
        float v[16];
        const int kg = k0 + ah * 16;
        if (ASRC == 0) {
#pragma unroll
            for (int q = 0; q < 4; q++)
                *(float4*)&v[q * 4] = *(const float4*)(A + (size_t)am * K + kg + q * 4);
        } else if (ASRC == 1) {
            const float p = pd[am];
#pragma unroll
            for (int q = 0; q < 16; q++)
                v[q] = fmaxf(fmaf(p, W1f[kg + q], b1f[kg + q]), 0.f);
        } else {
            if (kg < HD) {
#pragma unroll
                for (int q = 0; q < 4; q++) {
                    float4 xv = *(const float4*)(A + (size_t)rr * HD + kg + q * 4);
                    float4 yv = *(const float4*)(A + (size_t)cc * HD + kg + q * 4);
                    v[q*4+0] = xv.x * yv.x; v[q*4+1] = xv.y * yv.y;
                    v[q*4+2] = xv.z * yv.z; v[q*4+3] = xv.w * yv.w;
                }
            } else {
#pragma unroll
                for (int q = 0; q < 4; q++)
                    *(float4*)&v[q * 4] = *(const float4*)(extra2 + (size_t)am * HD + kg - HD + q * 4);
            }
        }
        uint32_t av[16];
#pragma unroll
        for (int q = 0; q < 16; q++) av[q] = f2tf(v[q]);

        // ---- stage B: already tf32-rounded fp32 bits ----
        uint4 bv[4];
#pragma unroll
        for (int q = 0; q < 4; q++)
            bv[q] = *(const uint4*)(Bt + (size_t)(n0 + ar) * K + kg + q * 4);

        __syncthreads();
        {
            uint32_t* da = sA + ar * SKA + ah * 16;
#pragma unroll
            for (int q = 0; q < 4; q++) *(uint4*)(da + q * 4) = *(uint4*)&av[q * 4];
            uint32_t* db = sB + ar * SKA + ah * 16;
#pragma unroll
            for (int q = 0; q < 4; q++) *(uint4*)(db + q * 4) = bv[q];
        }
        __syncthreads();

        // ---- compute: 4 k-steps of 8 ----
#pragma unroll
        for (int kq = 0; kq < 4; kq++) {
            uint32_t af[4][4];
#pragma unroll
            for (int mi = 0; mi < 4; mi++) {
                const int base = (wy * 64 + mi * 16 + (lane >> 2)) * SKA + kq * 8 + (lane & 3);
                af[mi][0] = sA[base];
                af[mi][1] = sA[base + 8 * SKA];
                af[mi][2] = sA[base + 4];
                af[mi][3] = sA[base + 8 * SKA + 4];
            }
            uint32_t bfr[4][2];
#pragma unroll
            for (int nq = 0; nq < 4; nq++) {
                const int base = (wx * 32 + nq * 8 + (lane >> 2)) * SKA + kq * 8 + (lane & 3);
                bfr[nq][0] = sB[base];
                bfr[nq][1] = sB[base + 4];
            }
#pragma unroll
            for (int mi = 0; mi < 4; mi++)
#pragma unroll
                for (int nq = 0; nq < 4; nq++)
                    mma_tf32(acc[mi][nq], af[mi][0], af[mi][1], af[mi][2], af[mi][3],
                             bfr[nq][0], bfr[nq][1]);
        }
    }

    // ---- epilogue ----
    const int lr = lane >> 2, lc = (lane & 3) * 2;
#pragma unroll
    for (int mi = 0; mi < 4; mi++) {
        const int r0 = m0 + wy * 64 + mi * 16 + lr;
        const int r1 = r0 + 8;
        const float* em0 = nullptr; const float* em1 = nullptr;
        if (MODE == 2) {
            em0 = extra + (size_t)gidx[r0] * N;
            em1 = extra + (size_t)gidx[r1] * N;
        }
#pragma unroll
        for (int nq = 0; nq < 4; nq++) {
            const int col = n0 + wx * 32 + nq * 8 + lc;
            float2 bv = *(const float2*)(bias + col);
            float v00 = acc[mi][nq][0] + bv.x, v01 = acc[mi][nq][1] + bv.y;
            float v10 = acc[mi][nq][2] + bv.x, v11 = acc[mi][nq][3] + bv.y;
            if (MODE == 2) {
                float2 e0 = *(const float2*)(em0 + col);
                float2 e1 = *(const float2*)(em1 + col);
                v00 *= e0.x; v01 *= e0.y; v10 *= e1.x; v11 *= e1.y;
            } else {
                if (RELU) {
                    v00 = fmaxf(v00, 0.f); v01 = fmaxf(v01, 0.f);
                    v10 = fmaxf(v10, 0.f); v11 = fmaxf(v11, 0.f);
                }
                if (MODE == 1) {
                    float2 x0 = *(const float2*)(extra + (size_t)r0 * N + col);
                    float2 x1 = *(const float2*)(extra + (size_t)r1 * N + col);
                    v00 += x0.x; v01 += x0.y; v10 += x1.x; v11 += x1.y;
                }
            }
            *(float2*)(C + (size_t)r0 * N + col) = make_float2(v00, v01);
            *(float2*)(C + (size_t)r1 * N + col) = make_float2(v10, v11);
        }
    }
}

// ---------------- weight transpose + tf32 preround ----------------
__global__ void convW(const float* __restrict__ inW2,
                      const float* __restrict__ gW1, const float* __restrict__ gW2,
                      const float* __restrict__ oW1, const float* __restrict__ oW2) {
    int idx = blockIdx.x * 256 + threadIdx.x;
    if (idx >= W_TOTAL) return;
    float val;
    size_t dst;
    if (idx < 589824) {
        int w = idx >> 16, local = idx & 65535;
        int k = local >> 8, n = local & 255;
        const float* src = (w == 0) ? inW2
                         : (w <= 4) ? gW1 + (size_t)(w - 1) * 65536
                                    : gW2 + (size_t)(w - 5) * 65536;
        val = src[k * 256 + n];
        dst = (size_t)w * 65536 + n * 256 + k;
    } else if (idx < W_O2) {
        int local = idx - W_O1;
        int k = local >> 8, n = local & 255;           // K=512, N=256
        val = oW1[(size_t)k * 256 + n];
        dst = W_O1 + (size_t)n * 512 + k;
    } else {
        int local = idx - W_O2;
        int k = local >> 7, n = local & 127;           // K=256, N=128
        val = oW2[(size_t)k * 128 + n];
        dst = W_O2 + (size_t)n * 256 + k;
    }
    g_W[dst] = __uint_as_float(f2tf(val));
}

// ---------------- elementwise / graph kernels (fp32, proven R8) ------------
__global__ void edge_geom(const int* __restrict__ ei, const int* __restrict__ n2g,
                          const int* __restrict__ nl, const float* __restrict__ pos,
                          const float* __restrict__ dn, const float* __restrict__ sig,
                          int E) {
    int e = blockIdx.x * 256 + threadIdx.x;
    if (e >= E) return;
    int r = ei[e], c = ei[E + e];
    float dx = pos[3*r]   - pos[3*c];
    float dy = pos[3*r+1] - pos[3*c+1];
    float dz = pos[3*r+2] - pos[3*c+2];
    float d  = sqrtf(dx*dx + dy*dy + dz*dz);
    float us = sig[nl[n2g[r]]];
    g_pd[e] = fmaf(dn[e], us, d);
}

__global__ void init_x(const int* __restrict__ atom, const float* __restrict__ nemb) {
    int i = blockIdx.x, k = threadIdx.x;
    g_x[(size_t)i * HD + k] = nemb[(size_t)atom[i] * HD + k];
}

__global__ void csr_zero(int N) {
    int i = blockIdx.x * 256 + threadIdx.x;
    if (i < N) g_cnt[i] = 0;
}

__global__ void csr_fill(const int* __restrict__ ei, int E) {
    int e = blockIdx.x * 256 + threadIdx.x;
    if (e >= E) return;
    int c = ei[E + e];
    int s = atomicAdd(&g_cnt[c], 1);
    if (s < MAXDEG) g_csr[c * MAXDEG + s] = e;
}

__global__ void csr_sort(int N) {
    int i = blockIdx.x * 256 + threadIdx.x;
    if (i >= N) return;
    int c = g_cnt[i]; if (c > MAXDEG) { c = MAXDEG; g_cnt[i] = MAXDEG; }
    int* p = &g_csr[i * MAXDEG];
    for (int a = 1; a < c; a++) {
        int v = p[a], b = a - 1;
        while (b >= 0 && p[b] > v) { p[b+1] = p[b]; b--; }
        p[b+1] = v;
    }
}

// xa[i] = x[i] + sum_{e: col(e)=i} relu(x[row(e)] + ea[e])
__global__ void agg_xa(const int* __restrict__ ei) {
    int i = blockIdx.x, k = threadIdx.x;
    float s = g_x[(size_t)i * HD + k];
    int c = g_cnt[i];
#pragma unroll 1
    for (int d = 0; d < c; d++) {
        int e = g_csr[i * MAXDEG + d];
        int r = ei[e];
        s += fmaxf(g_x[(size_t)r * HD + k] + g_ea[(size_t)e * HD + k], 0.f);
    }
    g_xa[(size_t)i * HD + k] = s;
}

__global__ void zero_out(float* out, int G) {
    int i = blockIdx.x * 256 + threadIdx.x;
    if (i < G) out[i] = 0.f;
}

// s = dot(s2[e], W3) + b3 ; loss = 0.5*(s + dn[e])^2 -> atomicAdd(out[graph])
__global__ void edge_loss(const float* __restrict__ W3, const float* __restrict__ b3,
                          const float* __restrict__ dn, const int* __restrict__ ei,
                          const int* __restrict__ n2g, float* __restrict__ out, int E) {
    __shared__ float w3[HD/2];
    int t = threadIdx.x;
    if (t < HD/2) w3[t] = W3[t];
    __syncthreads();
    int warp = t >> 5, lane = t & 31;
    int e = blockIdx.x * 8 + warp;
    if (e >= E) return;
    const float* p = g_s2 + (size_t)e * (HD/2);
    float s = 0.f;
#pragma unroll
    for (int i = 0; i < 4; i++) s += p[lane + 32*i] * w3[lane + 32*i];
#pragma unroll
    for (int o = 16; o; o >>= 1) s += __shfl_xor_sync(0xFFFFFFFFu, s, o);
    if (lane == 0) {
        s += b3[0];
        float d = s + dn[e];
        atomicAdd(&out[n2g[ei[e]]], 0.5f * d * d);
    }
}

// ---------------- launch ----------------
extern "C" void kernel_launch(void* const* d_in, const int* in_sizes, int n_in,
                              void* d_out, int out_size) {
    const int*   atom = (const int*)  d_in[0];
    const int*   ei   = (const int*)  d_in[1];
    const int*   et   = (const int*)  d_in[2];
    const int*   n2g  = (const int*)  d_in[3];
    const int*   nl   = (const int*)  d_in[4];
    const float* pos  = (const float*)d_in[5];
    const float* dn   = (const float*)d_in[6];
    const float* sig  = (const float*)d_in[7];
    const float* nemb = (const float*)d_in[8];
    const float* eemb = (const float*)d_in[9];
    const float* inW1 = (const float*)d_in[10];
    const float* inb1 = (const float*)d_in[11];
    const float* inW2 = (const float*)d_in[12];
    const float* inb2 = (const float*)d_in[13];
    const float* gW1  = (const float*)d_in[14];
    const float* gb1  = (const float*)d_in[15];
    const float* gW2  = (const float*)d_in[16];
    const float* gb2  = (const float*)d_in[17];
    const float* oW1  = (const float*)d_in[18];
    const float* ob1  = (const float*)d_in[19];
    const float* oW2  = (const float*)d_in[20];
    const float* ob2  = (const float*)d_in[21];
    const float* oW3  = (const float*)d_in[22];
    const float* ob3  = (const float*)d_in[23];
    float* out = (float*)d_out;

    const int N = in_sizes[0];
    const int E = in_sizes[2];
    const int G = out_size;

    float *p_pd, *p_ea, *p_x, *p_xa, *p_t, *p_s1, *p_s2, *p_W;
    cudaGetSymbolAddress((void**)&p_pd, g_pd);
    cudaGetSymbolAddress((void**)&p_ea, g_ea);
    cudaGetSymbolAddress((void**)&p_x,  g_x);
    cudaGetSymbolAddress((void**)&p_xa, g_xa);
    cudaGetSymbolAddress((void**)&p_t,  g_t);
    cudaGetSymbolAddress((void**)&p_s1, g_s1);
    cudaGetSymbolAddress((void**)&p_s2, g_s2);
    cudaGetSymbolAddress((void**)&p_W,  g_W);

    dim3 gE(HD / 128, E / 128);        // [E,256]
    dim3 gN(HD / 128, N / 128);        // [N,256]
    dim3 gS2(1, E / 128);              // [E,128]

    // weights -> transposed tf32-rounded fp32
    convW<<<(W_TOTAL + 255) / 256, 256>>>(inW2, gW1, gW2, oW1, oW2);

    // edge features: ea = (relu(pd @ W1 + b1) @ W2 + b2) * eemb[et]
    edge_geom<<<(E + 255) / 256, 256>>>(ei, n2g, nl, pos, dn, sig, E);
    tgemm<2, false, 1><<<gE, 256>>>(nullptr, p_W + W_IN2, inb2, p_ea, E, HD, HD,
                                    eemb, et, p_pd, inW1, inb1, nullptr, 0, nullptr);

    // node init + CSR
    init_x<<<N, HD>>>(atom, nemb);
    csr_zero<<<(N + 255) / 256, 256>>>(N);
    csr_fill<<<(E + 255) / 256, 256>>>(ei, E);
    csr_sort<<<(N + 255) / 256, 256>>>(N);

    // GIN convs
    for (int c = 0; c < 4; c++) {
        agg_xa<<<N, HD>>>(ei);
        tgemm<0, true, 0><<<gN, 256>>>(p_xa, p_W + W_G1(c), gb1 + c * HD, p_t,
                                       N, HD, HD, nullptr, nullptr,
                                       nullptr, nullptr, nullptr, nullptr, 0, nullptr);
        if (c < 3)
            tgemm<1, true, 0><<<gN, 256>>>(p_t, p_W + W_G2(c), gb2 + c * HD, p_x,
                                           N, HD, HD, p_x, nullptr,
                                           nullptr, nullptr, nullptr, nullptr, 0, nullptr);
        else
            tgemm<1, false, 0><<<gN, 256>>>(p_t, p_W + W_G2(c), gb2 + c * HD, p_x,
                                            N, HD, HD, p_x, nullptr,
                                            nullptr, nullptr, nullptr, nullptr, 0, nullptr);
    }

    // edge score head (feat gathered on-the-fly)
    tgemm<0, true, 2><<<gE, 256>>>(p_x, p_W + W_O1, ob1, p_s1, E, HD, 2 * HD,
                                   nullptr, nullptr, nullptr, nullptr, nullptr, ei, E, p_ea);
    tgemm<0, true, 0><<<gS2, 256>>>(p_s1, p_W + W_O2, ob2, p_s2, E, HD / 2, HD,
                                    nullptr, nullptr, nullptr, nullptr, nullptr, nullptr, 0, nullptr);

    zero_out<<<(G + 255) / 256, 256>>>(out, G);
    edge_loss<<<(E + 7) / 8, 256>>>(oW3, ob3, dn, ei, n2g, out, E);
}